// round 7
// baseline (speedup 1.0000x reference)
#include <cuda_runtime.h>
#include <math.h>

#define N_NODES 50000
#define N_EDGES 800000
#define NF 64

__device__ __align__(16) float g_phi[N_NODES * 3 * NF];    // 38.4 MB

// ---------- f32x2 helpers ----------
__device__ __forceinline__ unsigned long long pack2(float lo, float hi) {
    unsigned long long r;
    asm("mov.b64 %0, {%1, %2};" : "=l"(r) : "f"(lo), "f"(hi));
    return r;
}
__device__ __forceinline__ float2 unpack2(unsigned long long x) {
    float2 f;
    asm("mov.b64 {%0, %1}, %2;" : "=f"(f.x), "=f"(f.y) : "l"(x));
    return f;
}
#define FMA2(d, a, b, c) \
    asm("fma.rn.f32x2 %0, %1, %2, %3;" : "=l"(d) : "l"(a), "l"(b), "l"(c))

__device__ __forceinline__ void red_add_v4(float* p, float a, float b, float c, float d) {
    asm volatile("red.global.add.v4.f32 [%0], {%1, %2, %3, %4};"
                 :: "l"(p), "f"(a), "f"(b), "f"(c), "f"(d) : "memory");
}

// ---------- Kernel 0: out = [s | v] ----------
__global__ void k_init(const float4* __restrict__ s4, const float4* __restrict__ v4,
                       float4* __restrict__ out4) {
    const int NS4 = N_NODES * NF / 4;
    const int NV4 = N_NODES * 3 * NF / 4;
    int i = blockIdx.x * 256 + threadIdx.x;
    if (i < NS4) {
        out4[i] = s4[i];
    } else {
        int k = i - NS4;
        if (k < NV4) out4[NS4 + k] = v4[k];
    }
}

// ---------- Fused node kernel: phi = silu(s@W1+b1)@W2 + b2 ----------
// 16 nodes/block, 256 threads. h stays in smem (no g_h round trip).
__global__ void __launch_bounds__(256) k_node(
    const float* __restrict__ s, const float* __restrict__ W1,
    const float* __restrict__ b1, const float* __restrict__ W2,
    const float* __restrict__ b2) {
    __shared__ float sW1[NF * NF];       // 16 KB
    __shared__ float sS[16 * NF];        // 4 KB
    __shared__ float sH[16 * NF];        // 4 KB
    __shared__ float sW2[NF * 192];      // 48 KB

    int tid = threadIdx.x;
    int node0 = blockIdx.x * 16;
    for (int i = tid; i < NF * NF; i += 256) sW1[i] = W1[i];
    for (int i = tid; i < 16 * NF; i += 256) sS[i] = s[node0 * NF + i];
    for (int i = tid; i < NF * 192; i += 256) sW2[i] = W2[i];
    __syncthreads();

    int c = tid & 63;
    int q = tid >> 6;   // node quartet (4 nodes each)

    // Phase 1: h = silu(s @ W1 + b1)
    {
        float b = b1[c];
        float a0 = b, a1 = b, a2 = b, a3 = b;
        const float* sr = &sS[q * 4 * NF];
#pragma unroll 8
        for (int k = 0; k < NF; k++) {
            float w = sW1[k * NF + c];
            a0 += sr[k] * w;
            a1 += sr[NF + k] * w;
            a2 += sr[2 * NF + k] * w;
            a3 += sr[3 * NF + k] * w;
        }
        int o = q * 4 * NF + c;
        sH[o]          = a0 / (1.f + expf(-a0));
        sH[o + NF]     = a1 / (1.f + expf(-a1));
        sH[o + 2 * NF] = a2 / (1.f + expf(-a2));
        sH[o + 3 * NF] = a3 / (1.f + expf(-a3));
    }
    __syncthreads();

    // Phase 2: phi = h @ W2 + b2. Thread (c,q): 3 sections x 4 nodes.
    float acc[3][4];
#pragma unroll
    for (int sec = 0; sec < 3; sec++) {
        float b = b2[sec * NF + c];
#pragma unroll
        for (int n = 0; n < 4; n++) acc[sec][n] = b;
    }
    const float* hr = &sH[q * 4 * NF];
#pragma unroll 4
    for (int k = 0; k < NF; k++) {
        float h0 = hr[k], h1 = hr[NF + k], h2 = hr[2 * NF + k], h3 = hr[3 * NF + k];
#pragma unroll
        for (int sec = 0; sec < 3; sec++) {
            float w = sW2[k * 192 + sec * NF + c];
            acc[sec][0] += h0 * w;
            acc[sec][1] += h1 * w;
            acc[sec][2] += h2 * w;
            acc[sec][3] += h3 * w;
        }
    }
#pragma unroll
    for (int sec = 0; sec < 3; sec++)
#pragma unroll
        for (int n = 0; n < 4; n++)
            g_phi[(node0 + q * 4 + n) * 192 + sec * NF + c] = acc[sec][n];
}

// ---------- Fused edge kernel ----------
// 64 edges/block, 512 threads, 2 edges/thread. launch_bounds(512,2): 64-reg cap
// -> 2 CTAs/SM = 32 warps (50% occ) to hide gather latency.
__global__ void __launch_bounds__(512, 2) k_edge(
    const float* __restrict__ v, const float* __restrict__ radial,
    const float* __restrict__ f_cut, const float* __restrict__ uvec,
    const int* __restrict__ eidx, const float* __restrict__ Wr,
    const float* __restrict__ br, float* __restrict__ out) {
    __shared__ __align__(16) float sWr[32 * 192];  // 24 KB
    __shared__ __align__(16) float sBr[192];
    __shared__ float sRad[64 * 33];                // padded
    __shared__ int sI[64], sJ[64];
    __shared__ float sFc[64];
    __shared__ float sU[64 * 3];

    int tid = threadIdx.x;
    int e0 = blockIdx.x * 64;

    for (int i = tid; i < 32 * 192; i += 512) sWr[i] = Wr[i];
    if (tid < 192) sBr[tid] = br[tid];
    for (int i = tid; i < 64 * 32; i += 512) {
        int e = i >> 5, r = i & 31;
        sRad[e * 33 + r] = radial[(size_t)e0 * 32 + i];
    }
    if (tid < 64) {
        sI[tid] = eidx[e0 + tid];
        sJ[tid] = eidx[N_EDGES + e0 + tid];
        sFc[tid] = f_cut[e0 + tid];
    }
    if (tid >= 256 && tid < 256 + 192) sU[tid - 256] = uvec[(size_t)e0 * 3 + (tid - 256)];
    __syncthreads();

    int g = tid & 15;   // channel group: 4 channels per section
    int eq = tid >> 4;  // 0..31, edges 2*eq and 2*eq+1

    const unsigned long long* sBr64 = (const unsigned long long*)sBr;
    unsigned long long b0 = sBr64[2 * g],       b1 = sBr64[2 * g + 1];
    unsigned long long b2_ = sBr64[32 + 2 * g], b3 = sBr64[33 + 2 * g];
    unsigned long long b4 = sBr64[64 + 2 * g],  b5 = sBr64[65 + 2 * g];

    unsigned long long acc[2][6];
#pragma unroll
    for (int e = 0; e < 2; e++) {
        acc[e][0] = b0; acc[e][1] = b1; acc[e][2] = b2_;
        acc[e][3] = b3; acc[e][4] = b4; acc[e][5] = b5;
    }

    const unsigned long long* sWr64 = (const unsigned long long*)sWr;
#pragma unroll 4
    for (int r = 0; r < 32; r++) {
        int wb = r * 96 + 2 * g;
        unsigned long long w0 = sWr64[wb],      w1 = sWr64[wb + 1];
        unsigned long long w2 = sWr64[wb + 32], w3 = sWr64[wb + 33];
        unsigned long long w4 = sWr64[wb + 64], w5 = sWr64[wb + 65];
#pragma unroll
        for (int e = 0; e < 2; e++) {
            float rad = sRad[(eq * 2 + e) * 33 + r];
            unsigned long long rr = pack2(rad, rad);
            FMA2(acc[e][0], rr, w0, acc[e][0]);
            FMA2(acc[e][1], rr, w1, acc[e][1]);
            FMA2(acc[e][2], rr, w2, acc[e][2]);
            FMA2(acc[e][3], rr, w3, acc[e][3]);
            FMA2(acc[e][4], rr, w4, acc[e][4]);
            FMA2(acc[e][5], rr, w5, acc[e][5]);
        }
    }

    // Per-edge epilogue: gathers up front, then math + reductions.
#pragma unroll
    for (int e = 0; e < 2; e++) {
        int el = eq * 2 + e;
        int i = sI[el], j = sJ[el];
        float fc = sFc[el];

        const float4* pj = (const float4*)&g_phi[j * 192 + 4 * g];
        const float4* vj = (const float4*)&v[(size_t)j * 192 + 4 * g];
        float4 ps  = pj[0];
        float4 pv  = pj[16];
        float4 px  = pj[32];
        float4 vd0 = vj[0];
        float4 vd1 = vj[16];
        float4 vd2 = vj[32];

        float2 a0 = unpack2(acc[e][0]), a1 = unpack2(acc[e][1]);
        float xs0 = ps.x * (a0.x * fc), xs1 = ps.y * (a0.y * fc);
        float xs2 = ps.z * (a1.x * fc), xs3 = ps.w * (a1.y * fc);
        red_add_v4(out + i * NF + 4 * g, xs0, xs1, xs2, xs3);

        float2 a2 = unpack2(acc[e][2]), a3 = unpack2(acc[e][3]);
        float xvv0 = pv.x * (a2.x * fc), xvv1 = pv.y * (a2.y * fc);
        float xvv2 = pv.z * (a3.x * fc), xvv3 = pv.w * (a3.y * fc);

        float2 a4 = unpack2(acc[e][4]), a5 = unpack2(acc[e][5]);
        float xvs0 = px.x * (a4.x * fc), xvs1 = px.y * (a4.y * fc);
        float xvs2 = px.z * (a5.x * fc), xvs3 = px.w * (a5.y * fc);

        float u0 = sU[el * 3 + 0], u1 = sU[el * 3 + 1], u2 = sU[el * 3 + 2];
        float* ov = out + N_NODES * NF + i * 192 + 4 * g;

        red_add_v4(ov,
                   vd0.x * xvv0 + xvs0 * u0, vd0.y * xvv1 + xvs1 * u0,
                   vd0.z * xvv2 + xvs2 * u0, vd0.w * xvv3 + xvs3 * u0);
        red_add_v4(ov + 64,
                   vd1.x * xvv0 + xvs0 * u1, vd1.y * xvv1 + xvs1 * u1,
                   vd1.z * xvv2 + xvs2 * u1, vd1.w * xvv3 + xvs3 * u1);
        red_add_v4(ov + 128,
                   vd2.x * xvv0 + xvs0 * u2, vd2.y * xvv1 + xvs1 * u2,
                   vd2.z * xvv2 + xvs2 * u2, vd2.w * xvv3 + xvs3 * u2);
    }
}

extern "C" void kernel_launch(void* const* d_in, const int* in_sizes, int n_in,
                              void* d_out, int out_size) {
    const float* s      = (const float*)d_in[0];
    const float* v      = (const float*)d_in[1];
    const float* radial = (const float*)d_in[2];
    const float* f_cut  = (const float*)d_in[3];
    const float* uvec   = (const float*)d_in[4];
    const int*   eidx   = (const int*)d_in[5];
    const float* W1     = (const float*)d_in[6];
    const float* b1     = (const float*)d_in[7];
    const float* W2     = (const float*)d_in[8];
    const float* b2     = (const float*)d_in[9];
    const float* Wr     = (const float*)d_in[10];
    const float* br     = (const float*)d_in[11];
    float* out = (float*)d_out;

    k_init<<<(N_NODES * NF + N_NODES * 3 * NF) / 4 / 256, 256>>>(
        (const float4*)s, (const float4*)v, (float4*)out);
    k_node<<<N_NODES / 16, 256>>>(s, W1, b1, W2, b2);
    k_edge<<<N_EDGES / 64, 512>>>(v, radial, f_cut, uvec, eidx, Wr, br, out);
}

// round 8
// speedup vs baseline: 1.3453x; 1.3453x over previous
#include <cuda_runtime.h>
#include <math.h>

#define N_NODES 50000
#define N_EDGES 800000
#define NF 64
#define N_TILES (N_EDGES / 64)       // 12500 edge tiles
#define N_NTILES (N_NODES / 16)      // 3125 node tiles
#define GRID_PERS 444                // 148 SMs * 3 CTAs

__device__ __align__(16) float g_phi[N_NODES * 3 * NF];    // 38.4 MB

// ---------- f32x2 helpers ----------
__device__ __forceinline__ unsigned long long pack2(float lo, float hi) {
    unsigned long long r;
    asm("mov.b64 %0, {%1, %2};" : "=l"(r) : "f"(lo), "f"(hi));
    return r;
}
__device__ __forceinline__ float2 unpack2(unsigned long long x) {
    float2 f;
    asm("mov.b64 {%0, %1}, %2;" : "=f"(f.x), "=f"(f.y) : "l"(x));
    return f;
}
#define FMA2(d, a, b, c) \
    asm("fma.rn.f32x2 %0, %1, %2, %3;" : "=l"(d) : "l"(a), "l"(b), "l"(c))

__device__ __forceinline__ void red_add_v4(float* p, float a, float b, float c, float d) {
    asm volatile("red.global.add.v4.f32 [%0], {%1, %2, %3, %4};"
                 :: "l"(p), "f"(a), "f"(b), "f"(c), "f"(d) : "memory");
}

// ---------- Kernel 0: out = [s | v] ----------
__global__ void k_init(const float4* __restrict__ s4, const float4* __restrict__ v4,
                       float4* __restrict__ out4) {
    const int NS4 = N_NODES * NF / 4;
    const int NV4 = N_NODES * 3 * NF / 4;
    int i = blockIdx.x * 256 + threadIdx.x;
    if (i < NS4) {
        out4[i] = s4[i];
    } else {
        int k = i - NS4;
        if (k < NV4) out4[NS4 + k] = v4[k];
    }
}

// ---------- Persistent fused node kernel: phi = silu(s@W1+b1)@W2 + b2 ----------
// W1+W2 loaded once per block; grid-stride over 16-node tiles.
__global__ void __launch_bounds__(256) k_node(
    const float* __restrict__ s, const float* __restrict__ W1,
    const float* __restrict__ b1, const float* __restrict__ W2,
    const float* __restrict__ b2) {
    __shared__ float sW1[NF * NF];       // 16 KB
    __shared__ float sW2[NF * 192];      // 48 KB
    __shared__ float sS[16 * NF];        // 4 KB
    __shared__ float sH[16 * NF];        // 4 KB

    int tid = threadIdx.x;
    for (int i = tid; i < NF * NF; i += 256) sW1[i] = W1[i];
    for (int i = tid; i < NF * 192; i += 256) sW2[i] = W2[i];

    int c = tid & 63;
    int q = tid >> 6;
    float bb1 = b1[c];
    float bs = b2[c], bv = b2[NF + c], bx = b2[2 * NF + c];

    for (int tile = blockIdx.x; tile < N_NTILES; tile += GRID_PERS) {
        int node0 = tile * 16;
        __syncthreads();  // protect sS/sH from previous iteration's readers
        for (int i = tid; i < 16 * NF; i += 256) sS[i] = s[node0 * NF + i];
        __syncthreads();

        // Phase 1: h = silu(s @ W1 + b1)
        {
            float a0 = bb1, a1 = bb1, a2 = bb1, a3 = bb1;
            const float* sr = &sS[q * 4 * NF];
#pragma unroll 8
            for (int k = 0; k < NF; k++) {
                float w = sW1[k * NF + c];
                a0 += sr[k] * w;
                a1 += sr[NF + k] * w;
                a2 += sr[2 * NF + k] * w;
                a3 += sr[3 * NF + k] * w;
            }
            int o = q * 4 * NF + c;
            sH[o]          = a0 / (1.f + expf(-a0));
            sH[o + NF]     = a1 / (1.f + expf(-a1));
            sH[o + 2 * NF] = a2 / (1.f + expf(-a2));
            sH[o + 3 * NF] = a3 / (1.f + expf(-a3));
        }
        __syncthreads();

        // Phase 2: phi = h @ W2 + b2
        float acc[3][4];
#pragma unroll
        for (int n = 0; n < 4; n++) {
            acc[0][n] = bs; acc[1][n] = bv; acc[2][n] = bx;
        }
        const float* hr = &sH[q * 4 * NF];
#pragma unroll 4
        for (int k = 0; k < NF; k++) {
            float h0 = hr[k], h1 = hr[NF + k], h2 = hr[2 * NF + k], h3 = hr[3 * NF + k];
#pragma unroll
            for (int sec = 0; sec < 3; sec++) {
                float w = sW2[k * 192 + sec * NF + c];
                acc[sec][0] += h0 * w;
                acc[sec][1] += h1 * w;
                acc[sec][2] += h2 * w;
                acc[sec][3] += h3 * w;
            }
        }
#pragma unroll
        for (int sec = 0; sec < 3; sec++)
#pragma unroll
            for (int n = 0; n < 4; n++)
                g_phi[(node0 + q * 4 + n) * 192 + sec * NF + c] = acc[sec][n];
    }
}

// ---------- Persistent fused edge kernel ----------
// R6 geometry (64 edges/tile, 256 threads, 4 edges/thread, 12ch/thread) but
// grid-stride persistent: Wr (24KB) + bias loaded ONCE per block instead of
// per tile (removes 300MB L2 traffic + ~1/3 of per-block L1 wavefronts).
__global__ void __launch_bounds__(256, 3) k_edge(
    const float* __restrict__ v, const float* __restrict__ radial,
    const float* __restrict__ f_cut, const float* __restrict__ uvec,
    const int* __restrict__ eidx, const float* __restrict__ Wr,
    const float* __restrict__ br, float* __restrict__ out) {
    __shared__ __align__(16) float sWr[32 * 192];  // 24 KB
    __shared__ __align__(16) float sBr[192];
    __shared__ float sRad[64 * 33];                // padded
    __shared__ int sI[64], sJ[64];
    __shared__ float sFc[64];
    __shared__ float sU[64 * 3];

    int tid = threadIdx.x;

    for (int i = tid; i < 32 * 192; i += 256) sWr[i] = Wr[i];
    if (tid < 192) sBr[tid] = br[tid];
    __syncthreads();

    int g = tid & 15;   // channel group: 4 channels per section
    int eq = tid >> 4;  // edge quartet

    const unsigned long long* sBr64 = (const unsigned long long*)sBr;
    unsigned long long b0 = sBr64[2 * g],       b1 = sBr64[2 * g + 1];
    unsigned long long b2_ = sBr64[32 + 2 * g], b3 = sBr64[33 + 2 * g];
    unsigned long long b4 = sBr64[64 + 2 * g],  b5 = sBr64[65 + 2 * g];
    const unsigned long long* sWr64 = (const unsigned long long*)sWr;

    for (int tile = blockIdx.x; tile < N_TILES; tile += GRID_PERS) {
        int e0 = tile * 64;
        for (int i = tid; i < 64 * 32; i += 256) {
            int e = i >> 5, r = i & 31;
            sRad[e * 33 + r] = radial[(size_t)e0 * 32 + i];
        }
        if (tid < 64) {
            sI[tid] = eidx[e0 + tid];
            sJ[tid] = eidx[N_EDGES + e0 + tid];
            sFc[tid] = f_cut[e0 + tid];
        }
        if (tid >= 64 && tid < 64 + 192) sU[tid - 64] = uvec[(size_t)e0 * 3 + (tid - 64)];
        __syncthreads();

        unsigned long long acc[4][6];
#pragma unroll
        for (int e = 0; e < 4; e++) {
            acc[e][0] = b0; acc[e][1] = b1; acc[e][2] = b2_;
            acc[e][3] = b3; acc[e][4] = b4; acc[e][5] = b5;
        }

#pragma unroll 4
        for (int r = 0; r < 32; r++) {
            int wb = r * 96 + 2 * g;
            unsigned long long w0 = sWr64[wb],      w1 = sWr64[wb + 1];
            unsigned long long w2 = sWr64[wb + 32], w3 = sWr64[wb + 33];
            unsigned long long w4 = sWr64[wb + 64], w5 = sWr64[wb + 65];
#pragma unroll
            for (int e = 0; e < 4; e++) {
                float rad = sRad[(eq * 4 + e) * 33 + r];
                unsigned long long rr = pack2(rad, rad);
                FMA2(acc[e][0], rr, w0, acc[e][0]);
                FMA2(acc[e][1], rr, w1, acc[e][1]);
                FMA2(acc[e][2], rr, w2, acc[e][2]);
                FMA2(acc[e][3], rr, w3, acc[e][3]);
                FMA2(acc[e][4], rr, w4, acc[e][4]);
                FMA2(acc[e][5], rr, w5, acc[e][5]);
            }
        }

        // Per-edge epilogue: gathers up front, then math + reductions.
#pragma unroll
        for (int e = 0; e < 4; e++) {
            int el = eq * 4 + e;
            int i = sI[el], j = sJ[el];
            float fc = sFc[el];

            const float4* pj = (const float4*)&g_phi[j * 192 + 4 * g];
            const float4* vj = (const float4*)&v[(size_t)j * 192 + 4 * g];
            float4 ps  = pj[0];
            float4 pv  = pj[16];
            float4 px  = pj[32];
            float4 vd0 = vj[0];
            float4 vd1 = vj[16];
            float4 vd2 = vj[32];

            float2 a0 = unpack2(acc[e][0]), a1 = unpack2(acc[e][1]);
            float xs0 = ps.x * (a0.x * fc), xs1 = ps.y * (a0.y * fc);
            float xs2 = ps.z * (a1.x * fc), xs3 = ps.w * (a1.y * fc);
            red_add_v4(out + i * NF + 4 * g, xs0, xs1, xs2, xs3);

            float2 a2 = unpack2(acc[e][2]), a3 = unpack2(acc[e][3]);
            float xvv0 = pv.x * (a2.x * fc), xvv1 = pv.y * (a2.y * fc);
            float xvv2 = pv.z * (a3.x * fc), xvv3 = pv.w * (a3.y * fc);

            float2 a4 = unpack2(acc[e][4]), a5 = unpack2(acc[e][5]);
            float xvs0 = px.x * (a4.x * fc), xvs1 = px.y * (a4.y * fc);
            float xvs2 = px.z * (a5.x * fc), xvs3 = px.w * (a5.y * fc);

            float u0 = sU[el * 3 + 0], u1 = sU[el * 3 + 1], u2 = sU[el * 3 + 2];
            float* ov = out + N_NODES * NF + i * 192 + 4 * g;

            red_add_v4(ov,
                       vd0.x * xvv0 + xvs0 * u0, vd0.y * xvv1 + xvs1 * u0,
                       vd0.z * xvv2 + xvs2 * u0, vd0.w * xvv3 + xvs3 * u0);
            red_add_v4(ov + 64,
                       vd1.x * xvv0 + xvs0 * u1, vd1.y * xvv1 + xvs1 * u1,
                       vd1.z * xvv2 + xvs2 * u1, vd1.w * xvv3 + xvs3 * u1);
            red_add_v4(ov + 128,
                       vd2.x * xvv0 + xvs0 * u2, vd2.y * xvv1 + xvs1 * u2,
                       vd2.z * xvv2 + xvs2 * u2, vd2.w * xvv3 + xvs3 * u2);
        }
        __syncthreads();  // protect sRad/sI/sJ/sU before next tile's loads
    }
}

extern "C" void kernel_launch(void* const* d_in, const int* in_sizes, int n_in,
                              void* d_out, int out_size) {
    const float* s      = (const float*)d_in[0];
    const float* v      = (const float*)d_in[1];
    const float* radial = (const float*)d_in[2];
    const float* f_cut  = (const float*)d_in[3];
    const float* uvec   = (const float*)d_in[4];
    const int*   eidx   = (const int*)d_in[5];
    const float* W1     = (const float*)d_in[6];
    const float* b1     = (const float*)d_in[7];
    const float* W2     = (const float*)d_in[8];
    const float* b2     = (const float*)d_in[9];
    const float* Wr     = (const float*)d_in[10];
    const float* br     = (const float*)d_in[11];
    float* out = (float*)d_out;

    k_init<<<(N_NODES * NF + N_NODES * 3 * NF) / 4 / 256, 256>>>(
        (const float4*)s, (const float4*)v, (float4*)out);
    k_node<<<GRID_PERS, 256>>>(s, W1, b1, W2, b2);
    k_edge<<<GRID_PERS, 256>>>(v, radial, f_cut, uvec, eidx, Wr, br, out);
}

// round 9
// speedup vs baseline: 1.6476x; 1.2247x over previous
#include <cuda_runtime.h>
#include <math.h>
#include <stdint.h>

#define N_NODES 50000
#define N_EDGES 800000
#define NF 64
#define N_TILES (N_EDGES / 64)       // 12500 edge tiles
#define N_NTILES (N_NODES / 16)      // 3125 node tiles
#define GRID_NODE 444                // 148 SMs * 3 CTAs
#define GRID_EDGE 296                // 148 SMs * 2 CTAs (smem-limited)

#define SWR_STRIDE 200               // 32 x 200 tf32 bits  (banks 8k+n: conflict-free)
#define SRAD_STRIDE 40               // 64 x 40 tf32 bits   (banks 8row+kc: conflict-free)
#define SW_STRIDE 200                // 64 x 200 f32 W tile

__device__ __align__(16) float g_phi[N_NODES * 3 * NF];    // 38.4 MB

__device__ __forceinline__ uint32_t f2tf32(float f) {
    uint32_t r;
    asm("cvt.rna.tf32.f32 %0, %1;" : "=r"(r) : "f"(f));
    return r;
}

__device__ __forceinline__ void mma_tf32(float c[4], const uint32_t a[4],
                                         uint32_t b0, uint32_t b1) {
    asm("mma.sync.aligned.m16n8k8.row.col.f32.tf32.tf32.f32 "
        "{%0,%1,%2,%3}, {%4,%5,%6,%7}, {%8,%9}, {%0,%1,%2,%3};"
        : "+f"(c[0]), "+f"(c[1]), "+f"(c[2]), "+f"(c[3])
        : "r"(a[0]), "r"(a[1]), "r"(a[2]), "r"(a[3]), "r"(b0), "r"(b1));
}

__device__ __forceinline__ void red_add_v4(float* p, float a, float b, float c, float d) {
    asm volatile("red.global.add.v4.f32 [%0], {%1, %2, %3, %4};"
                 :: "l"(p), "f"(a), "f"(b), "f"(c), "f"(d) : "memory");
}

// ---------- Kernel 0: out = [s | v] ----------
__global__ void k_init(const float4* __restrict__ s4, const float4* __restrict__ v4,
                       float4* __restrict__ out4) {
    const int NS4 = N_NODES * NF / 4;
    const int NV4 = N_NODES * 3 * NF / 4;
    int i = blockIdx.x * 256 + threadIdx.x;
    if (i < NS4) {
        out4[i] = s4[i];
    } else {
        int k = i - NS4;
        if (k < NV4) out4[NS4 + k] = v4[k];
    }
}

// ---------- Persistent fused node kernel (unchanged from R8, fp32) ----------
__global__ void __launch_bounds__(256) k_node(
    const float* __restrict__ s, const float* __restrict__ W1,
    const float* __restrict__ b1, const float* __restrict__ W2,
    const float* __restrict__ b2) {
    __shared__ float sW1[NF * NF];
    __shared__ float sW2[NF * 192];
    __shared__ float sS[16 * NF];
    __shared__ float sH[16 * NF];

    int tid = threadIdx.x;
    for (int i = tid; i < NF * NF; i += 256) sW1[i] = W1[i];
    for (int i = tid; i < NF * 192; i += 256) sW2[i] = W2[i];

    int c = tid & 63;
    int q = tid >> 6;
    float bb1 = b1[c];
    float bs = b2[c], bv = b2[NF + c], bx = b2[2 * NF + c];

    for (int tile = blockIdx.x; tile < N_NTILES; tile += GRID_NODE) {
        int node0 = tile * 16;
        __syncthreads();
        for (int i = tid; i < 16 * NF; i += 256) sS[i] = s[node0 * NF + i];
        __syncthreads();

        {
            float a0 = bb1, a1 = bb1, a2 = bb1, a3 = bb1;
            const float* sr = &sS[q * 4 * NF];
#pragma unroll 8
            for (int k = 0; k < NF; k++) {
                float w = sW1[k * NF + c];
                a0 += sr[k] * w;
                a1 += sr[NF + k] * w;
                a2 += sr[2 * NF + k] * w;
                a3 += sr[3 * NF + k] * w;
            }
            int o = q * 4 * NF + c;
            sH[o]          = a0 / (1.f + expf(-a0));
            sH[o + NF]     = a1 / (1.f + expf(-a1));
            sH[o + 2 * NF] = a2 / (1.f + expf(-a2));
            sH[o + 3 * NF] = a3 / (1.f + expf(-a3));
        }
        __syncthreads();

        float acc[3][4];
#pragma unroll
        for (int n = 0; n < 4; n++) {
            acc[0][n] = bs; acc[1][n] = bv; acc[2][n] = bx;
        }
        const float* hr = &sH[q * 4 * NF];
#pragma unroll 4
        for (int k = 0; k < NF; k++) {
            float h0 = hr[k], h1 = hr[NF + k], h2 = hr[2 * NF + k], h3 = hr[3 * NF + k];
#pragma unroll
            for (int sec = 0; sec < 3; sec++) {
                float w = sW2[k * 192 + sec * NF + c];
                acc[sec][0] += h0 * w;
                acc[sec][1] += h1 * w;
                acc[sec][2] += h2 * w;
                acc[sec][3] += h3 * w;
            }
        }
#pragma unroll
        for (int sec = 0; sec < 3; sec++)
#pragma unroll
            for (int n = 0; n < 4; n++)
                g_phi[(node0 + q * 4 + n) * 192 + sec * NF + c] = acc[sec][n];
    }
}

// ---------- Persistent edge kernel: tf32 tensor-core radial GEMM + scatter ----------
// Per 64-edge tile: 8 warps do (64x32)@(32x192) via mma.sync tf32 -> sW smem,
// then the R8 epilogue (gather phi[j]/v[j], scale, red.v4 scatter) reads sW.
__global__ void __launch_bounds__(256) k_edge(
    const float* __restrict__ v, const float* __restrict__ radial,
    const float* __restrict__ f_cut, const float* __restrict__ uvec,
    const int* __restrict__ eidx, const float* __restrict__ Wr,
    const float* __restrict__ br, float* __restrict__ out) {
    __shared__ uint32_t sWrT[32 * SWR_STRIDE];        // 25.6 KB tf32 bits
    __shared__ uint32_t sRadT[64 * SRAD_STRIDE];      // 10.2 KB tf32 bits
    __shared__ __align__(16) float sW[64 * SW_STRIDE]; // 51.2 KB
    __shared__ int sI[64], sJ[64];
    __shared__ float sFc[64];
    __shared__ float sU[64 * 3];

    int tid = threadIdx.x;

    // Wr -> smem as tf32 bits, once per persistent block
    for (int i = tid; i < 32 * 192; i += 256) {
        int r = i / 192, c = i % 192;
        sWrT[r * SWR_STRIDE + c] = f2tf32(Wr[i]);
    }

    // GEMM warp mapping
    int wid = tid >> 5, lane = tid & 31;
    int mt = wid & 3;        // m-tile: edges 16*mt .. 16*mt+15
    int nh = wid >> 2;       // n-half: cols 96*nh .. 96*nh+95
    int rlo = mt * 16 + (lane >> 2);
    int kc = lane & 3;
    int nb = nh * 96 + (lane >> 2);   // B-frag col

    // Epilogue mapping (identical to R8)
    int g = tid & 15;
    int eq = tid >> 4;
    float4 Bs = *(const float4*)&br[4 * g];
    float4 Bv = *(const float4*)&br[NF + 4 * g];
    float4 Bx = *(const float4*)&br[2 * NF + 4 * g];

    __syncthreads();

    for (int tile = blockIdx.x; tile < N_TILES; tile += GRID_EDGE) {
        int e0 = tile * 64;
        for (int i = tid; i < 64 * 32; i += 256) {
            int e = i >> 5, r = i & 31;
            sRadT[e * SRAD_STRIDE + r] = f2tf32(radial[(size_t)e0 * 32 + i]);
        }
        if (tid < 64) {
            sI[tid] = eidx[e0 + tid];
            sJ[tid] = eidx[N_EDGES + e0 + tid];
            sFc[tid] = f_cut[e0 + tid];
        }
        if (tid >= 64 && tid < 64 + 192) sU[tid - 64] = uvec[(size_t)e0 * 3 + (tid - 64)];
        __syncthreads();

        // ---- tf32 GEMM: W' = rad @ Wr ----
        uint32_t a[4][4];
#pragma unroll
        for (int ks = 0; ks < 4; ks++) {
            int col = ks * 8 + kc;
            a[ks][0] = sRadT[rlo * SRAD_STRIDE + col];
            a[ks][1] = sRadT[(rlo + 8) * SRAD_STRIDE + col];
            a[ks][2] = sRadT[rlo * SRAD_STRIDE + col + 4];
            a[ks][3] = sRadT[(rlo + 8) * SRAD_STRIDE + col + 4];
        }

        float c[12][4];
#pragma unroll
        for (int nt = 0; nt < 12; nt++) {
            c[nt][0] = 0.f; c[nt][1] = 0.f; c[nt][2] = 0.f; c[nt][3] = 0.f;
            int ncol = nb + nt * 8;
#pragma unroll
            for (int ks = 0; ks < 4; ks++) {
                uint32_t b0 = sWrT[(ks * 8 + kc) * SWR_STRIDE + ncol];
                uint32_t b1 = sWrT[(ks * 8 + kc + 4) * SWR_STRIDE + ncol];
                mma_tf32(c[nt], a[ks], b0, b1);
            }
        }

        // store C frags to sW
#pragma unroll
        for (int nt = 0; nt < 12; nt++) {
            int col = nh * 96 + nt * 8 + (lane & 3) * 2;
            *(float2*)&sW[rlo * SW_STRIDE + col] = make_float2(c[nt][0], c[nt][1]);
            *(float2*)&sW[(rlo + 8) * SW_STRIDE + col] = make_float2(c[nt][2], c[nt][3]);
        }
        __syncthreads();

        // ---- epilogue: gather, scale, scatter (R8 structure) ----
#pragma unroll
        for (int e = 0; e < 4; e++) {
            int el = eq * 4 + e;
            int i = sI[el], j = sJ[el];
            float fc = sFc[el];

            const float4* pj = (const float4*)&g_phi[j * 192 + 4 * g];
            const float4* vj = (const float4*)&v[(size_t)j * 192 + 4 * g];
            float4 ps  = pj[0];
            float4 pv  = pj[16];
            float4 px  = pj[32];
            float4 vd0 = vj[0];
            float4 vd1 = vj[16];
            float4 vd2 = vj[32];

            const float* wrow = &sW[el * SW_STRIDE + 4 * g];
            float4 wsv = *(const float4*)wrow;
            float4 wvv = *(const float4*)(wrow + 64);
            float4 wxv = *(const float4*)(wrow + 128);

            float xs0 = ps.x * ((wsv.x + Bs.x) * fc), xs1 = ps.y * ((wsv.y + Bs.y) * fc);
            float xs2 = ps.z * ((wsv.z + Bs.z) * fc), xs3 = ps.w * ((wsv.w + Bs.w) * fc);
            red_add_v4(out + i * NF + 4 * g, xs0, xs1, xs2, xs3);

            float xvv0 = pv.x * ((wvv.x + Bv.x) * fc), xvv1 = pv.y * ((wvv.y + Bv.y) * fc);
            float xvv2 = pv.z * ((wvv.z + Bv.z) * fc), xvv3 = pv.w * ((wvv.w + Bv.w) * fc);

            float xvs0 = px.x * ((wxv.x + Bx.x) * fc), xvs1 = px.y * ((wxv.y + Bx.y) * fc);
            float xvs2 = px.z * ((wxv.z + Bx.z) * fc), xvs3 = px.w * ((wxv.w + Bx.w) * fc);

            float u0 = sU[el * 3 + 0], u1 = sU[el * 3 + 1], u2 = sU[el * 3 + 2];
            float* ov = out + N_NODES * NF + i * 192 + 4 * g;

            red_add_v4(ov,
                       vd0.x * xvv0 + xvs0 * u0, vd0.y * xvv1 + xvs1 * u0,
                       vd0.z * xvv2 + xvs2 * u0, vd0.w * xvv3 + xvs3 * u0);
            red_add_v4(ov + 64,
                       vd1.x * xvv0 + xvs0 * u1, vd1.y * xvv1 + xvs1 * u1,
                       vd1.z * xvv2 + xvs2 * u1, vd1.w * xvv3 + xvs3 * u1);
            red_add_v4(ov + 128,
                       vd2.x * xvv0 + xvs0 * u2, vd2.y * xvv1 + xvs1 * u2,
                       vd2.z * xvv2 + xvs2 * u2, vd2.w * xvv3 + xvs3 * u2);
        }
        __syncthreads();
    }
}

extern "C" void kernel_launch(void* const* d_in, const int* in_sizes, int n_in,
                              void* d_out, int out_size) {
    const float* s      = (const float*)d_in[0];
    const float* v      = (const float*)d_in[1];
    const float* radial = (const float*)d_in[2];
    const float* f_cut  = (const float*)d_in[3];
    const float* uvec   = (const float*)d_in[4];
    const int*   eidx   = (const int*)d_in[5];
    const float* W1     = (const float*)d_in[6];
    const float* b1     = (const float*)d_in[7];
    const float* W2     = (const float*)d_in[8];
    const float* b2     = (const float*)d_in[9];
    const float* Wr     = (const float*)d_in[10];
    const float* br     = (const float*)d_in[11];
    float* out = (float*)d_out;

    k_init<<<(N_NODES * NF + N_NODES * 3 * NF) / 4 / 256, 256>>>(
        (const float4*)s, (const float4*)v, (float4*)out);
    k_node<<<GRID_NODE, 256>>>(s, W1, b1, W2, b2);
    k_edge<<<GRID_EDGE, 256>>>(v, radial, f_cut, uvec, eidx, Wr, br, out);
}